// round 1
// baseline (speedup 1.0000x reference)
#include <cuda_runtime.h>
#include <math.h>

// Problem constants
#define BB   4
#define CI   256
#define CO   256
#define HH   64
#define WWD  64
#define HWSZ (HH*WWD)
#define KKT  9

// ---------------- scratch (device globals; no allocation) ----------------
__device__ float  g_xt[BB*HWSZ*CI];      // x in NHWC   (16.8 MB)
__device__ float  g_wt[KKT*CI*CO];       // weights [k][c][o]  (2.36 MB)
__device__ float4 g_pw[BB*KKT*HWSZ];     // premasked bilinear weights (w00,w01,w10,w11)
__device__ int4   g_po[BB*KKT*HWSZ];     // clamped corner element offsets ((y*64+x)*256)

// ---------------- f32x2 helpers ----------------
__device__ __forceinline__ unsigned long long pk2(float v) {
    unsigned long long r;
    asm("mov.b64 %0, {%1, %1};" : "=l"(r) : "f"(v));
    return r;
}
__device__ __forceinline__ void fma2(unsigned long long& d, unsigned long long a, unsigned long long b) {
    asm("fma.rn.f32x2 %0, %1, %2, %0;" : "+l"(d) : "l"(a), "l"(b));
}
__device__ __forceinline__ void unpk2(unsigned long long v, float& lo, float& hi) {
    asm("mov.b64 {%0, %1}, %2;" : "=f"(lo), "=f"(hi) : "l"(v));
}

// ---------------- kernel 1: NCHW -> NHWC transpose of x ----------------
__global__ void k_transpose_x(const float* __restrict__ x) {
    __shared__ float tile[32][33];
    int b  = blockIdx.z;
    int c0 = blockIdx.y * 32;
    int p0 = blockIdx.x * 32;
    int tx = threadIdx.x, ty = threadIdx.y;   // 32 x 8
    #pragma unroll
    for (int j = 0; j < 32; j += 8)
        tile[ty + j][tx] = x[((b*CI + c0 + ty + j)*HWSZ) + p0 + tx];
    __syncthreads();
    #pragma unroll
    for (int j = 0; j < 32; j += 8)
        g_xt[(b*HWSZ + p0 + ty + j)*CI + c0 + tx] = tile[tx][ty + j];
}

// ---------------- kernel 2: dcn_w [o][c][k] -> g_wt [k][c][o] ----------------
__global__ void k_transpose_w(const float* __restrict__ dw) {
    int idx = blockIdx.x * 256 + threadIdx.x;
    if (idx < KKT*CI*CO) {
        int k = idx / (CI*CO);
        int r = idx % (CI*CO);
        int c = r / CO;
        int o = r % CO;
        g_wt[idx] = dw[(o*CI + c)*KKT + k];
    }
}

// ---------------- kernel 3: offset conv (implicit GEMM, N=27) + param build ----------------
// grid: 128 blocks (b, pair of rows), 128 threads
__global__ __launch_bounds__(128) void k_offset(const float* __restrict__ x,
                                                const float* __restrict__ ow,
                                                const float* __restrict__ ob) {
    __shared__ float sA2[32][128];   // [c_local][pixel]
    __shared__ float sB2[32][32];    // [c_local][oc padded to 32]
    __shared__ float so[128][33];    // conv result per pixel

    int tid = threadIdx.x;
    int bid = blockIdx.x;
    int b   = bid >> 5;
    int h0  = (bid & 31) * 2;

    int pg = tid & 31;     // pixel group: pixels pg*4 .. pg*4+3
    int og = tid >> 5;     // oc group: ocs og*8 .. og*8+7

    int lh = tid >> 6;     // this thread's own pixel (for A loads + epilogue)
    int w  = tid & 63;

    unsigned long long acc[4][4];
    #pragma unroll
    for (int i = 0; i < 4; ++i)
        #pragma unroll
        for (int j = 0; j < 4; ++j) acc[i][j] = 0ULL;

    for (int tap = 0; tap < 9; ++tap) {
        int di = tap / 3 - 1, dj = tap % 3 - 1;
        int y  = h0 + lh + di;
        int xx = w + dj;
        bool inb = (y >= 0) && (y < HH) && (xx >= 0) && (xx < WWD);

        for (int cc = 0; cc < 8; ++cc) {
            int c0 = cc * 32;
            // A: x[b][c0+cl][y][xx] for this thread's pixel
            #pragma unroll
            for (int cl = 0; cl < 32; ++cl)
                sA2[cl][tid] = inb ? x[((b*CI + c0 + cl)*HH + y)*WWD + xx] : 0.0f;
            // B: offset_w[oc][c0+cl][tap], padded ocs -> 0
            #pragma unroll
            for (int q = 0; q < 8; ++q) {
                int i  = tid + q * 128;
                int cl = i >> 5;
                int oc = i & 31;
                sB2[cl][oc] = (oc < 27) ? ow[((oc*CI) + c0 + cl)*KKT + tap] : 0.0f;
            }
            __syncthreads();
            #pragma unroll 4
            for (int cl = 0; cl < 32; ++cl) {
                float4 av = *(const float4*)&sA2[cl][pg*4];
                unsigned long long a2[4];
                a2[0] = pk2(av.x); a2[1] = pk2(av.y); a2[2] = pk2(av.z); a2[3] = pk2(av.w);
                const unsigned long long* bp = (const unsigned long long*)&sB2[cl][og*8];
                unsigned long long b2[4];
                #pragma unroll
                for (int j = 0; j < 4; ++j) b2[j] = bp[j];
                #pragma unroll
                for (int i = 0; i < 4; ++i)
                    #pragma unroll
                    for (int j = 0; j < 4; ++j) fma2(acc[i][j], a2[i], b2[j]);
            }
            __syncthreads();
        }
    }

    // scatter accumulators to smem
    #pragma unroll
    for (int i = 0; i < 4; ++i) {
        int pix = pg*4 + i;
        #pragma unroll
        for (int j = 0; j < 4; ++j) {
            float lo, hi;
            unpk2(acc[i][j], lo, hi);
            so[pix][og*8 + 2*j]     = lo;
            so[pix][og*8 + 2*j + 1] = hi;
        }
    }
    __syncthreads();

    // per-pixel parameter build (this thread's own pixel)
    float ov[27];
    #pragma unroll
    for (int oc = 0; oc < 27; ++oc) ov[oc] = so[tid][oc] + ob[oc];

    int hh = h0 + lh;
    int hw = hh * WWD + w;
    #pragma unroll
    for (int kk = 0; kk < 9; ++kk) {
        float dy = ov[2*kk];
        float dx = ov[2*kk + 1];
        float m  = 1.0f / (1.0f + expf(-ov[18 + kk]));
        int ki = kk / 3, kj = kk % 3;
        float py = (float)(hh - 1 + ki) + dy;
        float px = (float)(w  - 1 + kj) + dx;
        float fy = floorf(py), fx = floorf(px);
        float wy = py - fy,    wx = px - fx;
        int y0 = (int)fy, x0 = (int)fx;
        int y1 = y0 + 1,  x1 = x0 + 1;

        bool vy0 = (y0 >= 0) && (y0 < HH);
        bool vy1 = (y1 >= 0) && (y1 < HH);
        bool vx0 = (x0 >= 0) && (x0 < WWD);
        bool vx1 = (x1 >= 0) && (x1 < WWD);

        float w00 = (1.0f - wy) * (1.0f - wx) * m * ((vy0 && vx0) ? 1.0f : 0.0f);
        float w01 = (1.0f - wy) * wx          * m * ((vy0 && vx1) ? 1.0f : 0.0f);
        float w10 = wy * (1.0f - wx)          * m * ((vy1 && vx0) ? 1.0f : 0.0f);
        float w11 = wy * wx                   * m * ((vy1 && vx1) ? 1.0f : 0.0f);

        int yc0 = min(max(y0, 0), HH - 1);
        int yc1 = min(max(y1, 0), HH - 1);
        int xc0 = min(max(x0, 0), WWD - 1);
        int xc1 = min(max(x1, 0), WWD - 1);

        int idx = ((b*KKT + kk)*HWSZ) + hw;
        g_pw[idx] = make_float4(w00, w01, w10, w11);
        g_po[idx] = make_int4((yc0*WWD + xc0)*CI, (yc0*WWD + xc1)*CI,
                              (yc1*WWD + xc0)*CI, (yc1*WWD + xc1)*CI);
    }
}

// ---------------- kernel 4: fused bilinear-sample + main GEMM ----------------
// grid: 256 blocks = (b, h row) -> Mtile = 64 pixels, Ntile = 256 (full COUT)
// K = 9 taps x 256 ch, chunks of 32
__global__ __launch_bounds__(256, 2) void k_main(float* __restrict__ out) {
    __shared__ float  sA[64][36];     // [pixel][c_local], 16B-aligned rows
    __shared__ float  sB[32][260];    // [c_local][o]
    __shared__ float4 sPw[64];
    __shared__ int4   sPo[64];

    int tid = threadIdx.x;
    int bid = blockIdx.x;
    int b = bid >> 6;
    int h = bid & 63;
    int hw0 = h * WWD;
    int xtbase = b * HWSZ * CI;

    int mt8 = (tid >> 5) * 8;     // this thread's 8 pixels
    int nt2 = (tid & 31) * 2;     // this thread's output-pair base (interleaved N)

    unsigned long long acc[8][4];
    #pragma unroll
    for (int i = 0; i < 8; ++i)
        #pragma unroll
        for (int j = 0; j < 4; ++j) acc[i][j] = 0ULL;

    // A-build thread mapping
    int clo  = (tid & 7) * 4;     // c offset within chunk (float4)
    int prow = tid >> 3;          // pixel 0..31 (x2 iterations)
    // B-load thread mapping
    int brow = tid >> 3;          // c row 0..31
    int bcol = (tid & 7) * 4;     // col base, stride 32 per q (bank-friendly)

    for (int k = 0; k < 9; ++k) {
        if (tid < 64) {
            int pidx = ((b*KKT + k)*HWSZ) + hw0 + tid;
            sPw[tid] = g_pw[pidx];
            sPo[tid] = g_po[pidx];
        }
        __syncthreads();

        for (int cc = 0; cc < 8; ++cc) {
            int c0 = cc * 32;

            // build A tile: gather 4 bilinear corners (contiguous in c), blend
            #pragma unroll
            for (int r = 0; r < 2; ++r) {
                int pix = prow + 32 * r;
                float4 wv = sPw[pix];
                int4   pv = sPo[pix];
                const float* xb = g_xt + xtbase + c0 + clo;
                float4 v00 = *(const float4*)(xb + pv.x);
                float4 v01 = *(const float4*)(xb + pv.y);
                float4 v10 = *(const float4*)(xb + pv.z);
                float4 v11 = *(const float4*)(xb + pv.w);
                float4 s;
                s.x = wv.x*v00.x + wv.y*v01.x + wv.z*v10.x + wv.w*v11.x;
                s.y = wv.x*v00.y + wv.y*v01.y + wv.z*v10.y + wv.w*v11.y;
                s.z = wv.x*v00.z + wv.y*v01.z + wv.z*v10.z + wv.w*v11.z;
                s.w = wv.x*v00.w + wv.y*v01.w + wv.z*v10.w + wv.w*v11.w;
                *(float4*)&sA[pix][clo] = s;
            }

            // load B tile: g_wt[(k*256 + c0+row)*256 + col], coalesced
            {
                const float* src = g_wt + ((k*CI + c0 + brow)*CO) + bcol;
                #pragma unroll
                for (int q = 0; q < 8; ++q)
                    *(float4*)&sB[brow][bcol + q*32] = *(const float4*)(src + q*32);
            }
            __syncthreads();

            // GEMM: 8 pixels x 8 outputs per thread, packed f32x2
            #pragma unroll 4
            for (int cl = 0; cl < 32; ++cl) {
                unsigned long long a2[8];
                #pragma unroll
                for (int i = 0; i < 8; ++i) a2[i] = pk2(sA[mt8 + i][cl]);
                unsigned long long bv[4];
                #pragma unroll
                for (int j = 0; j < 4; ++j)
                    bv[j] = *(const unsigned long long*)&sB[cl][nt2 + 64*j];
                #pragma unroll
                for (int i = 0; i < 8; ++i)
                    #pragma unroll
                    for (int j = 0; j < 4; ++j) fma2(acc[i][j], a2[i], bv[j]);
            }
            __syncthreads();
        }
    }

    // epilogue: out[b][n][h][w]
    #pragma unroll
    for (int i = 0; i < 8; ++i) {
        int pix = mt8 + i;
        int obase = (b*CO)*HWSZ + hw0 + pix;
        #pragma unroll
        for (int j = 0; j < 4; ++j) {
            float lo, hi;
            unpk2(acc[i][j], lo, hi);
            int n = nt2 + 64*j;
            out[obase + n*HWSZ]       = lo;
            out[obase + (n+1)*HWSZ]   = hi;
        }
    }
}

// ---------------- launch ----------------
extern "C" void kernel_launch(void* const* d_in, const int* in_sizes, int n_in,
                              void* d_out, int out_size) {
    (void)in_sizes; (void)n_in; (void)out_size;
    const float* x  = (const float*)d_in[0];   // (4,256,64,64)
    const float* ow = (const float*)d_in[1];   // (27,256,3,3)
    const float* ob = (const float*)d_in[2];   // (27,)
    const float* dw = (const float*)d_in[3];   // (256,256,3,3)
    float* out = (float*)d_out;                // (4,256,64,64)

    dim3 tb(32, 8);
    dim3 tg(HWSZ/32, CI/32, BB);
    k_transpose_x<<<tg, tb>>>(x);
    k_transpose_w<<<(KKT*CI*CO + 255)/256, 256>>>(dw);
    k_offset<<<128, 128>>>(x, ow, ob);
    k_main<<<256, 256>>>(out);
}